// round 10
// baseline (speedup 1.0000x reference)
#include <cuda_runtime.h>
#include <cuda_bf16.h>
#include <cstddef>

// Problem constants (fixed by the reference)
#define N_NODES 50000
#define N_EDGES 640000
#define D_FEAT  128
#define BM      64      // node rows per GEMM block
#define WPAD    132     // smem row stride (floats): 132 mod 32 = 4 -> quarter-warp
                        // strided-row LDS.128 tiles all 32 banks (conflict-free)

// Scratch for h_neighbor accumulation (no cudaMalloc allowed).
__device__ float g_hn[(size_t)N_NODES * D_FEAT];
// 1 if src/dst buffers are int64 (little-endian, high words zero), else int32.
__device__ int g_idx_is_64;

// ---------------------------------------------------------------------------
// Kernel 0: index-dtype detector.  int64 indices < 50000 have zero high
// words at every odd int32 position; int32 indices are random nonzero there.
// P(false positive) ~ (1/50000)^32 ~ 0.  Deterministic, graph-capturable.
// ---------------------------------------------------------------------------
__global__ void detect_dtype_kernel(const int* __restrict__ src_as_i32)
{
    if (threadIdx.x == 0 && blockIdx.x == 0) {
        int all_zero = 1;
        #pragma unroll
        for (int i = 1; i < 64; i += 2)
            if (src_as_i32[i] != 0) { all_zero = 0; break; }
        g_idx_is_64 = all_zero;
    }
}

// ---------------------------------------------------------------------------
// Kernel 1: edge scatter.  One warp per edge: gather h[src] row (32 x float4,
// coalesced 512B), scale by w[e], vector-reduce-add into g_hn[dst].
// red.global.add.v4.f32 (sm_90+) quarters the atomic lane-op count.
// Index dtype resolved at runtime via g_idx_is_64 (uniform branch).
// ---------------------------------------------------------------------------
__global__ __launch_bounds__(256) void scatter_kernel(
    const float* __restrict__ h,
    const float* __restrict__ w,
    const int*   __restrict__ src,
    const int*   __restrict__ dst,
    float* __restrict__ hn)
{
    int gw   = (blockIdx.x * blockDim.x + threadIdx.x) >> 5;   // global warp = edge id
    int lane = threadIdx.x & 31;
    if (gw >= N_EDGES) return;

    int s, d;
    if (g_idx_is_64) {
        s = (int)((const long long*)src)[gw];
        d = (int)((const long long*)dst)[gw];
    } else {
        s = src[gw];
        d = dst[gw];
    }
    if ((unsigned)s >= N_NODES || (unsigned)d >= N_NODES) return;  // defensive
    float we = __ldg(&w[gw]);

    float4 v = ((const float4*)(h + (size_t)s * D_FEAT))[lane];
    v.x *= we; v.y *= we; v.z *= we; v.w *= we;

    float* p = hn + (size_t)d * D_FEAT + lane * 4;
    asm volatile("red.global.add.v4.f32 [%0], {%1, %2, %3, %4};"
                 :: "l"(p), "f"(v.x), "f"(v.y), "f"(v.z), "f"(v.w)
                 : "memory");
}

// ---------------------------------------------------------------------------
// Kernel 2: fused dual-branch GEMM + leaky_relu, plus copy of h_neighbor to
// the output buffer.  Per block: 64 nodes x full K=128 x full N=128.
// smem: W1, W2 ([n][k], 128 x WPAD each) + X1 = h+hn, X2 = h*hn (BM x WPAD).
// Thread micro-tile: 4 node-rows x 8 STRIDED out-cols (c = tx + 16*j).
// Strided cols => adjacent lanes read adjacent W rows => bank stride 4 =>
// conflict-free quarter-warp LDS.128 phases.
// ---------------------------------------------------------------------------
__global__ __launch_bounds__(256, 1) void fused_gemm_kernel(
    const float* __restrict__ h,
    const float* __restrict__ hn,
    const float* __restrict__ W1,
    const float* __restrict__ W2,
    float* __restrict__ out_hn,     // may be null (single-output layout)
    float* __restrict__ out)
{
    extern __shared__ float sm[];
    float* W1s = sm;                         // 128 * WPAD
    float* W2s = W1s + 128 * WPAD;           // 128 * WPAD
    float* X1s = W2s + 128 * WPAD;           // BM  * WPAD
    float* X2s = X1s + BM * WPAD;            // BM  * WPAD

    const int tid  = threadIdx.x;
    const int base = blockIdx.x * BM;

    // --- stage weights: 128 rows x 32 float4 each ---
    #pragma unroll 4
    for (int i = tid; i < 128 * 32; i += 256) {
        int r = i >> 5, c4 = i & 31;
        float4 a = ((const float4*)W1)[i];
        float4 b = ((const float4*)W2)[i];
        *(float4*)&W1s[r * WPAD + c4 * 4] = a;
        *(float4*)&W2s[r * WPAD + c4 * 4] = b;
    }

    // --- stage X tiles; also emit h_neighbor rows to output half 1 ---
    #pragma unroll 2
    for (int i = tid; i < BM * 32; i += 256) {
        int r = i >> 5, c4 = i & 31;
        int node = base + r;
        float4 hv = make_float4(0.f, 0.f, 0.f, 0.f);
        float4 nv = make_float4(0.f, 0.f, 0.f, 0.f);
        if (node < N_NODES) {
            hv = ((const float4*)(h  + (size_t)node * D_FEAT))[c4];
            nv = ((const float4*)(hn + (size_t)node * D_FEAT))[c4];
            if (out_hn != nullptr)
                ((float4*)(out_hn + (size_t)node * D_FEAT))[c4] = nv;
        }
        *(float4*)&X1s[r * WPAD + c4 * 4] =
            make_float4(hv.x + nv.x, hv.y + nv.y, hv.z + nv.z, hv.w + nv.w);
        *(float4*)&X2s[r * WPAD + c4 * 4] =
            make_float4(hv.x * nv.x, hv.y * nv.y, hv.z * nv.z, hv.w * nv.w);
    }
    __syncthreads();

    // --- compute: tx in [0,16) selects strided cols {tx, tx+16, ...};
    //     ty in [0,16) selects 4 node-rows ---
    const int tx = tid & 15;
    const int ty = tid >> 4;
    const int r0 = ty * 4;

    float acc1[4][8];
    float acc2[4][8];
    #pragma unroll
    for (int i = 0; i < 4; i++)
        #pragma unroll
        for (int j = 0; j < 8; j++) { acc1[i][j] = 0.f; acc2[i][j] = 0.f; }

    #pragma unroll 1
    for (int k4 = 0; k4 < 32; k4++) {
        float4 x1[4], x2[4];
        #pragma unroll
        for (int i = 0; i < 4; i++) {
            x1[i] = *(const float4*)&X1s[(r0 + i) * WPAD + k4 * 4];
            x2[i] = *(const float4*)&X2s[(r0 + i) * WPAD + k4 * 4];
        }
        #pragma unroll
        for (int j = 0; j < 8; j++) {
            int c = tx + 16 * j;     // strided column
            float4 w1 = *(const float4*)&W1s[c * WPAD + k4 * 4];
            float4 w2 = *(const float4*)&W2s[c * WPAD + k4 * 4];
            #pragma unroll
            for (int i = 0; i < 4; i++) {
                acc1[i][j] += x1[i].x * w1.x;
                acc1[i][j] += x1[i].y * w1.y;
                acc1[i][j] += x1[i].z * w1.z;
                acc1[i][j] += x1[i].w * w1.w;
                acc2[i][j] += x2[i].x * w2.x;
                acc2[i][j] += x2[i].y * w2.y;
                acc2[i][j] += x2[i].z * w2.z;
                acc2[i][j] += x2[i].w * w2.w;
            }
        }
    }

    // --- epilogue: leaky_relu(add) + leaky_relu(mul); strided scalar stores
    //     (half-warp covers 16 consecutive floats -> full 64B sectors) ---
    #pragma unroll
    for (int i = 0; i < 4; i++) {
        int node = base + r0 + i;
        if (node >= N_NODES) continue;
        float* op = out + (size_t)node * D_FEAT + tx;
        #pragma unroll
        for (int j = 0; j < 8; j++) {
            float a = acc1[i][j];
            float b = acc2[i][j];
            float la = (a > 0.f) ? a : 0.01f * a;
            float lb = (b > 0.f) ? b : 0.01f * b;
            op[16 * j] = la + lb;
        }
    }
}

// ---------------------------------------------------------------------------
// Launch: detect idx dtype -> zero hn scratch -> scatter -> fused GEMM.
// All default-stream, graph-capturable (memsetAsync + kernel launches only).
// ---------------------------------------------------------------------------
extern "C" void kernel_launch(void* const* d_in, const int* in_sizes, int n_in,
                              void* d_out, int out_size)
{
    const float* nfeat = (const float*)d_in[0];
    const float* w     = (const float*)d_in[1];
    const float* W1    = (const float*)d_in[2];
    const float* W2    = (const float*)d_in[3];
    const int*   src   = (const int*)d_in[4];
    const int*   dst   = (const int*)d_in[5];

    float* hn_scratch = nullptr;
    cudaGetSymbolAddress((void**)&hn_scratch, g_hn);

    // resolve index dtype on-device (int32 vs int64)
    detect_dtype_kernel<<<1, 32>>>(src);

    // zero the h_neighbor accumulator
    cudaMemsetAsync(hn_scratch, 0, (size_t)N_NODES * D_FEAT * sizeof(float));

    // scatter: one warp per edge
    {
        int threads = 256;
        int warps_per_block = threads / 32;
        int blocks = (N_EDGES + warps_per_block - 1) / warps_per_block;
        scatter_kernel<<<blocks, threads>>>(nfeat, w, src, dst, hn_scratch);
    }

    // output layout: (h_neighbor, out) concatenated if out_size fits both
    const size_t ND = (size_t)N_NODES * D_FEAT;
    float* out_hn;
    float* out2;
    if ((size_t)out_size >= 2 * ND) {
        out_hn = (float*)d_out;
        out2   = (float*)d_out + ND;
    } else {
        out_hn = nullptr;               // single-output fallback
        out2   = (float*)d_out;
    }

    // fused dual GEMM + leaky_relu (+ hn copy-out)
    {
        static const size_t smem_bytes =
            (size_t)(2 * 128 + 2 * BM) * WPAD * sizeof(float);  // 202,752 B
        cudaFuncSetAttribute(fused_gemm_kernel,
                             cudaFuncAttributeMaxDynamicSharedMemorySize,
                             (int)smem_bytes);
        int blocks = (N_NODES + BM - 1) / BM;   // 782
        fused_gemm_kernel<<<blocks, 256, smem_bytes>>>(
            nfeat, hn_scratch, W1, W2, out_hn, out2);
    }
}

// round 17
// speedup vs baseline: 1.0347x; 1.0347x over previous
#include <cuda_runtime.h>
#include <cuda_bf16.h>
#include <cstddef>

// Problem constants (fixed by the reference)
#define N_NODES 50000
#define N_EDGES 640000
#define D_FEAT  128
#define BM      64      // node rows per GEMM block
#define WPAD    132     // smem row stride (floats): 132 mod 32 = 4 -> quarter-warp
                        // strided-row LDS.128 tiles all 32 banks (conflict-free)

typedef unsigned long long u64;

// Scratch for h_neighbor accumulation (no cudaMalloc allowed).
__device__ float g_hn[(size_t)N_NODES * D_FEAT];
// 1 if src/dst buffers are int64 (little-endian, high words zero), else int32.
__device__ int g_idx_is_64;

// Packed dual-fp32 FMA (sm_103a): d = a*b + c elementwise on two f32 lanes.
// ptxas never emits this from C++; inline PTX is required (2x fp32 throughput).
__device__ __forceinline__ u64 ffma2(u64 a, u64 b, u64 c) {
    u64 d;
    asm("fma.rn.f32x2 %0, %1, %2, %3;" : "=l"(d) : "l"(a), "l"(b), "l"(c));
    return d;
}
__device__ __forceinline__ float pair_sum(u64 v) {
    return __uint_as_float((unsigned)v) + __uint_as_float((unsigned)(v >> 32));
}

// ---------------------------------------------------------------------------
// Kernel 0: index-dtype detector.  int64 indices < 50000 have zero high
// words at every odd int32 position; int32 indices are random nonzero there.
// P(false positive) ~ (1/50000)^32 ~ 0.  Deterministic, graph-capturable.
// ---------------------------------------------------------------------------
__global__ void detect_dtype_kernel(const int* __restrict__ src_as_i32)
{
    if (threadIdx.x == 0 && blockIdx.x == 0) {
        int all_zero = 1;
        #pragma unroll
        for (int i = 1; i < 64; i += 2)
            if (src_as_i32[i] != 0) { all_zero = 0; break; }
        g_idx_is_64 = all_zero;
    }
}

// ---------------------------------------------------------------------------
// Kernel 1: edge scatter.  One warp per edge: gather h[src] row (32 x float4,
// coalesced 512B), scale by w[e], vector-reduce-add into g_hn[dst].
// red.global.add.v4.f32 (sm_90+) quarters the atomic lane-op count.
// Index dtype resolved at runtime via g_idx_is_64 (uniform branch).
// ---------------------------------------------------------------------------
__global__ __launch_bounds__(256) void scatter_kernel(
    const float* __restrict__ h,
    const float* __restrict__ w,
    const int*   __restrict__ src,
    const int*   __restrict__ dst,
    float* __restrict__ hn)
{
    int gw   = (blockIdx.x * blockDim.x + threadIdx.x) >> 5;   // global warp = edge id
    int lane = threadIdx.x & 31;
    if (gw >= N_EDGES) return;

    int s, d;
    if (g_idx_is_64) {
        s = (int)((const long long*)src)[gw];
        d = (int)((const long long*)dst)[gw];
    } else {
        s = src[gw];
        d = dst[gw];
    }
    if ((unsigned)s >= N_NODES || (unsigned)d >= N_NODES) return;  // defensive
    float we = __ldg(&w[gw]);

    float4 v = ((const float4*)(h + (size_t)s * D_FEAT))[lane];
    v.x *= we; v.y *= we; v.z *= we; v.w *= we;

    float* p = hn + (size_t)d * D_FEAT + lane * 4;
    asm volatile("red.global.add.v4.f32 [%0], {%1, %2, %3, %4};"
                 :: "l"(p), "f"(v.x), "f"(v.y), "f"(v.z), "f"(v.w)
                 : "memory");
}

// ---------------------------------------------------------------------------
// Kernel 2: fused dual-branch GEMM + leaky_relu via packed f32x2 FMA.
// Per block: 64 nodes x full K=128 x full N=128.
// smem: W1, W2 ([n][k], 128 x WPAD each) + X1 = h+hn, X2 = h*hn (BM x WPAD).
// Thread micro-tile: 4 node-rows x 8 STRIDED out-cols (c = tx + 16*j).
// k-pairing: LDS.128 read as ulonglong2 gives (k,k+1) f32x2 pairs for free;
// accumulators hold dual partial sums, reduced once in the epilogue.
// ---------------------------------------------------------------------------
__global__ __launch_bounds__(256, 1) void fused_gemm_kernel(
    const float* __restrict__ h,
    const float* __restrict__ hn,
    const float* __restrict__ W1,
    const float* __restrict__ W2,
    float* __restrict__ out_hn,     // may be null (single-output layout)
    float* __restrict__ out)
{
    extern __shared__ float sm[];
    float* W1s = sm;                         // 128 * WPAD
    float* W2s = W1s + 128 * WPAD;           // 128 * WPAD
    float* X1s = W2s + 128 * WPAD;           // BM  * WPAD
    float* X2s = X1s + BM * WPAD;            // BM  * WPAD

    const int tid  = threadIdx.x;
    const int base = blockIdx.x * BM;

    // --- stage weights: 128 rows x 32 float4 each ---
    #pragma unroll 4
    for (int i = tid; i < 128 * 32; i += 256) {
        int r = i >> 5, c4 = i & 31;
        float4 a = ((const float4*)W1)[i];
        float4 b = ((const float4*)W2)[i];
        *(float4*)&W1s[r * WPAD + c4 * 4] = a;
        *(float4*)&W2s[r * WPAD + c4 * 4] = b;
    }

    // --- stage X tiles; also emit h_neighbor rows to output half 1 ---
    #pragma unroll 2
    for (int i = tid; i < BM * 32; i += 256) {
        int r = i >> 5, c4 = i & 31;
        int node = base + r;
        float4 hv = make_float4(0.f, 0.f, 0.f, 0.f);
        float4 nv = make_float4(0.f, 0.f, 0.f, 0.f);
        if (node < N_NODES) {
            hv = ((const float4*)(h  + (size_t)node * D_FEAT))[c4];
            nv = ((const float4*)(hn + (size_t)node * D_FEAT))[c4];
            if (out_hn != nullptr)
                ((float4*)(out_hn + (size_t)node * D_FEAT))[c4] = nv;
        }
        *(float4*)&X1s[r * WPAD + c4 * 4] =
            make_float4(hv.x + nv.x, hv.y + nv.y, hv.z + nv.z, hv.w + nv.w);
        *(float4*)&X2s[r * WPAD + c4 * 4] =
            make_float4(hv.x * nv.x, hv.y * nv.y, hv.z * nv.z, hv.w * nv.w);
    }
    __syncthreads();

    // --- compute: tx in [0,16) selects strided cols {tx, tx+16, ...};
    //     ty in [0,16) selects 4 node-rows ---
    const int tx = tid & 15;
    const int ty = tid >> 4;
    const int r0 = ty * 4;

    u64 acc1[4][8];
    u64 acc2[4][8];
    #pragma unroll
    for (int i = 0; i < 4; i++)
        #pragma unroll
        for (int j = 0; j < 8; j++) { acc1[i][j] = 0ULL; acc2[i][j] = 0ULL; }

    #pragma unroll 1
    for (int k4 = 0; k4 < 32; k4++) {
        ulonglong2 x1p[4], x2p[4];           // each .x/.y is an f32x2 (k,k+1) pair
        #pragma unroll
        for (int i = 0; i < 4; i++) {
            x1p[i] = *(const ulonglong2*)&X1s[(r0 + i) * WPAD + k4 * 4];
            x2p[i] = *(const ulonglong2*)&X2s[(r0 + i) * WPAD + k4 * 4];
        }
        #pragma unroll
        for (int j = 0; j < 8; j++) {
            int c = tx + 16 * j;             // strided column
            ulonglong2 w1p = *(const ulonglong2*)&W1s[c * WPAD + k4 * 4];
            ulonglong2 w2p = *(const ulonglong2*)&W2s[c * WPAD + k4 * 4];
            #pragma unroll
            for (int i = 0; i < 4; i++) {
                acc1[i][j] = ffma2(x1p[i].x, w1p.x, acc1[i][j]);
                acc1[i][j] = ffma2(x1p[i].y, w1p.y, acc1[i][j]);
                acc2[i][j] = ffma2(x2p[i].x, w2p.x, acc2[i][j]);
                acc2[i][j] = ffma2(x2p[i].y, w2p.y, acc2[i][j]);
            }
        }
    }

    // --- epilogue: pair-reduce, leaky_relu(add) + leaky_relu(mul);
    //     strided scalar stores (half-warp = 16 consecutive floats/sector) ---
    #pragma unroll
    for (int i = 0; i < 4; i++) {
        int node = base + r0 + i;
        if (node >= N_NODES) continue;
        float* op = out + (size_t)node * D_FEAT + tx;
        #pragma unroll
        for (int j = 0; j < 8; j++) {
            float a = pair_sum(acc1[i][j]);
            float b = pair_sum(acc2[i][j]);
            float la = (a > 0.f) ? a : 0.01f * a;
            float lb = (b > 0.f) ? b : 0.01f * b;
            op[16 * j] = la + lb;
        }
    }
}

// ---------------------------------------------------------------------------
// Launch: detect idx dtype -> zero hn scratch -> scatter -> fused GEMM.
// All default-stream, graph-capturable (memsetAsync + kernel launches only).
// ---------------------------------------------------------------------------
extern "C" void kernel_launch(void* const* d_in, const int* in_sizes, int n_in,
                              void* d_out, int out_size)
{
    const float* nfeat = (const float*)d_in[0];
    const float* w     = (const float*)d_in[1];
    const float* W1    = (const float*)d_in[2];
    const float* W2    = (const float*)d_in[3];
    const int*   src   = (const int*)d_in[4];
    const int*   dst   = (const int*)d_in[5];

    float* hn_scratch = nullptr;
    cudaGetSymbolAddress((void**)&hn_scratch, g_hn);

    // resolve index dtype on-device (int32 vs int64)
    detect_dtype_kernel<<<1, 32>>>(src);

    // zero the h_neighbor accumulator
    cudaMemsetAsync(hn_scratch, 0, (size_t)N_NODES * D_FEAT * sizeof(float));

    // scatter: one warp per edge
    {
        int threads = 256;
        int warps_per_block = threads / 32;
        int blocks = (N_EDGES + warps_per_block - 1) / warps_per_block;
        scatter_kernel<<<blocks, threads>>>(nfeat, w, src, dst, hn_scratch);
    }

    // output layout: (h_neighbor, out) concatenated if out_size fits both
    const size_t ND = (size_t)N_NODES * D_FEAT;
    float* out_hn;
    float* out2;
    if ((size_t)out_size >= 2 * ND) {
        out_hn = (float*)d_out;
        out2   = (float*)d_out + ND;
    } else {
        out_hn = nullptr;               // single-output fallback
        out2   = (float*)d_out;
    }

    // fused dual GEMM + leaky_relu (+ hn copy-out)
    {
        static const size_t smem_bytes =
            (size_t)(2 * 128 + 2 * BM) * WPAD * sizeof(float);  // 202,752 B
        cudaFuncSetAttribute(fused_gemm_kernel,
                             cudaFuncAttributeMaxDynamicSharedMemorySize,
                             (int)smem_bytes);
        int blocks = (N_NODES + BM - 1) / BM;   // 782
        fused_gemm_kernel<<<blocks, 256, smem_bytes>>>(
            nfeat, hn_scratch, W1, W2, out_hn, out2);
    }
}